// round 7
// baseline (speedup 1.0000x reference)
#include <cuda_runtime.h>
#include <math.h>

#define T_LEN  2000
#define FC     514            // 257 * 2
#define NSER   8224           // 16 * 514
#define NPAIRS (NSER / 2)     // 4112 float2 series-pairs
#define FC2    (FC / 2)       // 257 pairs per row
#define CH     40             // number of time chunks
#define LCH    50             // chunk length (CH*LCH == T_LEN)
#define NBX    17             // ceil(NPAIRS / 256)

// Per-t constants: (w, a = 1-w, b = w*a, bP = b * Ppre_u).
__device__ float4 g_c4[T_LEN];
// Per-chunk constants: (P, gamma).
__device__ float2 g_ck[CH];
// Inclusive state published per (chunk, series): v2 and S.
__device__ float g_sv2[CH * NSER];
__device__ float g_ss [CH * NSER];
// Lookback flags, one per (chunk, x-block). Re-zeroed every launch.
__device__ int   g_flag[CH * NBX];

__device__ __forceinline__ int ld_acq(const int* p) {
    int v;
    asm volatile("ld.acquire.gpu.global.b32 %0, [%1];" : "=r"(v) : "l"(p) : "memory");
    return v;
}
__device__ __forceinline__ void st_rel(int* p, int v) {
    asm volatile("st.release.gpu.global.b32 [%0], %1;" :: "l"(p), "r"(v) : "memory");
}

// Integer-exponent power by binary exponentiation (FP64 pow() is poison).
__device__ __forceinline__ double dpow(double b, int e) {
    double r = 1.0, p = b;
    while (e) { if (e & 1) r *= p; p *= p; e >>= 1; }
    return r;
}

__global__ void coef_kernel() {
    int t = blockIdx.x * blockDim.x + threadIdx.x;
    if (t < CH * NBX) g_flag[t] = 0;           // reset lookback flags each launch
    if (t >= T_LEN) return;
    const double b  = (double)0.99f;
    const double c1 = (double)(1.0f - 0.99f);  // exact (Sterbenz)
    int u  = t % LCH;
    int t0 = t - u;

    double w  = c1 / (1.0 - dpow(b, t + 1));   // w_0 == 1 exactly
    double a  = 1.0 - w;
    double bb = w * a;
    double Ppre = (u == 0) ? 1.0
                : dpow(b, u) * (1.0 - dpow(b, t0)) / (1.0 - dpow(b, t));
    g_c4[t] = make_float4((float)w, (float)a, (float)bb, (float)(bb * Ppre));

    if (u == 0) {
        int c = t0 / LCH;
        double ratio = (1.0 - dpow(b, t0)) / (1.0 - dpow(b, t0 + LCH));
        double P     = dpow(b, LCH) * ratio;   // 0 for chunk 0
        double ga    = (c == 0) ? 0.0 : (P / dpow(b, t0)) * (1.0 - ratio);
        g_ck[c] = make_float2((float)P, (float)ga);
    }
}

// Fused single pass: pass1 -> lookback combine -> publish -> pass2.
// Grid (NBX, CH) = 680 blocks of 256 threads: fits in ONE wave
// (148 SMs x 8 blocks capacity = 1184), so spin-wait cannot deadlock.
__global__ __launch_bounds__(256)
void fused_kernel(const float* __restrict__ in, float* __restrict__ out) {
    int pr  = blockIdx.x * 256 + threadIdx.x;
    int c   = blockIdx.y;
    bool act = (pr < NPAIRS);

    int n = 0, fp = 0;
    if (act) { n = pr / FC2; fp = pr - n * FC2; }
    size_t base = ((size_t)n * T_LEN + (size_t)c * LCH) * FC2 + fp;
    const float2* xp = (const float2*)in  + base;
    float2*       yp = (float2*)out + base;
    const float4* cf = g_c4 + c * LCH;

    // ---- pass 1: chunk-local (Q, alpha, beta-hat) from zero start ----
    float Q0 = 0.f, Q1 = 0.f, al0 = 0.f, al1 = 0.f, be0 = 0.f, be1 = 0.f;
    if (act) {
#pragma unroll 10
        for (int u = 0; u < LCH; u++) {
            float4 k = __ldg(cf + u);            // (w, a, b, bP)
            float2 x = __ldg(xp + (size_t)u * FC2);
            float u0 = x.x - Q0;
            float u1 = x.y - Q1;
            Q0 = fmaf(k.x, u0, Q0);
            Q1 = fmaf(k.x, u1, Q1);
            al0 = fmaf(k.y, al0, (k.z * u0) * u0);
            al1 = fmaf(k.y, al1, (k.z * u1) * u1);
            be0 = fmaf(k.y, be0, k.w * u0);
            be1 = fmaf(k.y, be1, k.w * u1);
        }
    }

    // ---- lookback: wait for predecessor chunk's inclusive state ----
    float v20 = 0.f, v21 = 0.f, S0 = 0.f, S1 = 0.f;
    if (c > 0) {
        const int* fl = &g_flag[(c - 1) * NBX + blockIdx.x];
        while (ld_acq(fl) == 0) { __nanosleep(64); }
        if (act) {
            int pidx = (c - 1) * NSER + pr * 2;
            float2 pv = __ldcg((const float2*)&g_sv2[pidx]);
            float2 ps = __ldcg((const float2*)&g_ss [pidx]);
            v20 = pv.x; v21 = pv.y; S0 = ps.x; S1 = ps.y;
        }
    }

    // ---- publish own inclusive state ----
    float2 pg = __ldg(&g_ck[c]);                 // (P, gamma)
    if (act) {
        // S' = P*S + al + v2*(gamma*v2 - 2*be);  v2' = P*v2 + Q
        float c0 = fmaf(pg.y, v20, -2.0f * be0);
        float c1 = fmaf(pg.y, v21, -2.0f * be1);
        float nS0 = fmaf(pg.x, S0, fmaf(v20, c0, al0));
        float nS1 = fmaf(pg.x, S1, fmaf(v21, c1, al1));
        float nv0 = fmaf(pg.x, v20, Q0);
        float nv1 = fmaf(pg.x, v21, Q1);
        int idx = c * NSER + pr * 2;
        *(float2*)&g_sv2[idx] = make_float2(nv0, nv1);
        *(float2*)&g_ss [idx] = make_float2(nS0, nS1);
    }
    __syncthreads();
    if (threadIdx.x == 0) {
        __threadfence();
        st_rel(&g_flag[c * NBX + blockIdx.x], 1);
    }

    // ---- pass 2: replay chunk from exact start state, emit outputs ----
    if (act) {
#pragma unroll 10
        for (int u = 0; u < LCH; u++) {
            float4 k = __ldg(cf + u);            // (w, a, b, -)
            float2 x = __ldg(xp + (size_t)u * FC2);
            float d0 = x.x - v20;
            float d1 = x.y - v21;
            v20 = fmaf(k.x, d0, v20);
            v21 = fmaf(k.x, d1, v21);
            S0 = fmaf(k.y, S0, (k.z * d0) * d0);
            S1 = fmaf(k.y, S1, (k.z * d1) * d1);
            float r0 = rsqrtf(fmaxf(S0, 0.0f) + 1e-5f);
            float r1 = rsqrtf(fmaxf(S1, 0.0f) + 1e-5f);
            float2 y;
            y.x = (k.y * d0) * r0;
            y.y = (k.y * d1) * r1;
            __stcs(yp + (size_t)u * FC2, y);
        }
    }
}

extern "C" void kernel_launch(void* const* d_in, const int* in_sizes, int n_in,
                              void* d_out, int out_size) {
    const float* s = (const float*)d_in[0];
    float* out = (float*)d_out;
    coef_kernel<<<(T_LEN + 127) / 128, 128>>>();
    dim3 grid(NBX, CH);                          // (17, 40) = 680 blocks, one wave
    fused_kernel<<<grid, 256>>>(s, out);
}

// round 8
// speedup vs baseline: 1.9293x; 1.9293x over previous
#include <cuda_runtime.h>
#include <math.h>

#define T_LEN  2000
#define FC     514            // 257 * 2
#define NSER   8224           // 16 * 514
#define NPAIRS (NSER / 2)     // 4112 float2 series-pairs
#define FC2    (FC / 2)       // 257 pairs per row
#define CH     40             // number of time chunks
#define LCH    50             // chunk length (CH*LCH == T_LEN)
#define NBX    17             // ceil(NPAIRS / 256)

// Per (chunk, series) scratch.
__device__ float g_q [CH * NSER];
__device__ float g_al[CH * NSER];
__device__ float g_be[CH * NSER];
__device__ float g_v2[CH * NSER];
__device__ float g_s [CH * NSER];
// Completion counters per x-slice (zero-init; each launch resets them to 0).
__device__ int g_cnt[NBX];

// Integer-exponent power by binary exponentiation (FP64 pow() is poison).
__device__ __forceinline__ double dpow(double b, int e) {
    double r = 1.0, p = b;
    while (e) { if (e & 1) r *= p; p *= p; e >>= 1; }
    return r;
}

// Build chunk-local per-t coefficients (w, a, b, bP) into smem. 50 threads.
__device__ __forceinline__ void build_coefs(float4* sc, int c) {
    int u = threadIdx.x;
    if (u < LCH) {
        const double b  = (double)0.99f;
        const double c1 = (double)(1.0f - 0.99f);   // exact (Sterbenz)
        int t0 = c * LCH;
        int t  = t0 + u;
        double w  = c1 / (1.0 - dpow(b, t + 1));    // w_0 == 1 exactly
        double a  = 1.0 - w;
        double bb = w * a;
        double Ppre = (u == 0) ? 1.0
                    : dpow(b, u) * (1.0 - dpow(b, t0)) / (1.0 - dpow(b, t));
        sc[u] = make_float4((float)w, (float)a, (float)bb, (float)(bb * Ppre));
    }
}

// Kernel 1: pass1 (chunk-local transfer coeffs) + last-block combine tail.
__global__ __launch_bounds__(256)
void pass1_kernel(const float* __restrict__ in) {
    __shared__ float4 sc[LCH];
    __shared__ float2 sck[CH];       // (P, gamma) — combiner only
    __shared__ int sflag;
    int c = blockIdx.y;
    build_coefs(sc, c);
    __syncthreads();

    int pr = blockIdx.x * 256 + threadIdx.x;
    bool act = (pr < NPAIRS);
    if (act) {
        int n  = pr / FC2;
        int fp = pr - n * FC2;
        const float2* xp = (const float2*)in
                         + ((size_t)n * T_LEN + (size_t)c * LCH) * FC2 + fp;
        float Q0 = 0.f, Q1 = 0.f, al0 = 0.f, al1 = 0.f, be0 = 0.f, be1 = 0.f;
#pragma unroll 10
        for (int u = 0; u < LCH; u++) {
            float4 k = sc[u];                    // (w, a, b, bP)
            float2 x = __ldg(xp + (size_t)u * FC2);
            float u0 = x.x - Q0;
            float u1 = x.y - Q1;
            Q0 = fmaf(k.x, u0, Q0);
            Q1 = fmaf(k.x, u1, Q1);
            al0 = fmaf(k.y, al0, (k.z * u0) * u0);
            al1 = fmaf(k.y, al1, (k.z * u1) * u1);
            be0 = fmaf(k.y, be0, k.w * u0);
            be1 = fmaf(k.y, be1, k.w * u1);
        }
        int idx = c * NSER + pr * 2;
        *(float2*)&g_q [idx] = make_float2(Q0, Q1);
        *(float2*)&g_al[idx] = make_float2(al0, al1);
        *(float2*)&g_be[idx] = make_float2(be0, be1);
    }

    // Last block of this x-slice runs the combine (single handoff level).
    __threadfence();
    if (threadIdx.x == 0) {
        int old = atomicAdd(&g_cnt[blockIdx.x], 1);
        sflag = (old == CH - 1);
    }
    __syncthreads();
    if (!sflag) return;

    // Per-chunk constants (P, gamma), closed-form, into smem.
    if (threadIdx.x < CH) {
        const double b = (double)0.99f;
        int t0 = threadIdx.x * LCH;
        double ratio = (1.0 - dpow(b, t0)) / (1.0 - dpow(b, t0 + LCH));
        double P     = dpow(b, LCH) * ratio;    // 0 for chunk 0
        double ga    = (threadIdx.x == 0) ? 0.0
                     : (P / dpow(b, t0)) * (1.0 - ratio);
        sck[threadIdx.x] = make_float2((float)P, (float)ga);
    }
    __syncthreads();

    if (act) {
        float v20 = 0.f, v21 = 0.f, S0 = 0.f, S1 = 0.f;
#pragma unroll 8
        for (int k = 0; k < CH; k++) {
            int idx = k * NSER + pr * 2;
            float2 pg = sck[k];                  // (P, gamma)
            float2 q  = __ldcg((const float2*)&g_q [idx]);
            float2 al = __ldcg((const float2*)&g_al[idx]);
            float2 be = __ldcg((const float2*)&g_be[idx]);
            *(float2*)&g_v2[idx] = make_float2(v20, v21);
            *(float2*)&g_s [idx] = make_float2(S0, S1);
            // S' = P*S + al + v2*(gamma*v2 - 2*be);  v2' = P*v2 + Q
            float c0 = fmaf(pg.y, v20, -2.0f * be.x);
            float c1 = fmaf(pg.y, v21, -2.0f * be.y);
            S0 = fmaf(pg.x, S0, fmaf(v20, c0, al.x));
            S1 = fmaf(pg.x, S1, fmaf(v21, c1, al.y));
            v20 = fmaf(pg.x, v20, q.x);
            v21 = fmaf(pg.x, v21, q.y);
        }
    }
    // Reset counter for the next (graph-replayed) launch.
    if (threadIdx.x == 0) g_cnt[blockIdx.x] = 0;
}

// Kernel 2: pass2 — replay each chunk with exact start state, emit outputs.
__global__ __launch_bounds__(256)
void pass2_kernel(const float* __restrict__ in, float* __restrict__ out) {
    __shared__ float4 sc[LCH];
    int c = blockIdx.y;
    build_coefs(sc, c);
    __syncthreads();

    int pr = blockIdx.x * 256 + threadIdx.x;
    if (pr >= NPAIRS) return;
    int n  = pr / FC2;
    int fp = pr - n * FC2;
    size_t base = ((size_t)n * T_LEN + (size_t)c * LCH) * FC2 + fp;
    const float2* xp = (const float2*)in  + base;
    float2*       yp = (float2*)out + base;

    int idx = c * NSER + pr * 2;
    float2 v2 = __ldg((const float2*)&g_v2[idx]);
    float2 S  = __ldg((const float2*)&g_s [idx]);
    float v20 = v2.x, v21 = v2.y, S0 = S.x, S1 = S.y;

#pragma unroll 10
    for (int u = 0; u < LCH; u++) {
        float4 k = sc[u];                        // (w, a, b, -)
        float2 x = __ldg(xp + (size_t)u * FC2);
        float d0 = x.x - v20;
        float d1 = x.y - v21;
        v20 = fmaf(k.x, d0, v20);
        v21 = fmaf(k.x, d1, v21);
        S0 = fmaf(k.y, S0, (k.z * d0) * d0);
        S1 = fmaf(k.y, S1, (k.z * d1) * d1);
        float r0 = rsqrtf(fmaxf(S0, 0.0f) + 1e-5f);
        float r1 = rsqrtf(fmaxf(S1, 0.0f) + 1e-5f);
        float2 y;
        y.x = (k.y * d0) * r0;
        y.y = (k.y * d1) * r1;
        __stcs(yp + (size_t)u * FC2, y);
    }
}

extern "C" void kernel_launch(void* const* d_in, const int* in_sizes, int n_in,
                              void* d_out, int out_size) {
    const float* s = (const float*)d_in[0];
    float* out = (float*)d_out;
    dim3 grid(NBX, CH);                          // (17, 40)
    pass1_kernel<<<grid, 256>>>(s);
    pass2_kernel<<<grid, 256>>>(s, out);
}